// round 5
// baseline (speedup 1.0000x reference)
#include <cuda_runtime.h>
#include <cuda_bf16.h>

#define NTAGS 64
#define LOG2E 1.4426950408889634f
#define LN2   0.69314718055994531f

__device__ __forceinline__ float fast_ex2(float x) {
    float r; asm("ex2.approx.ftz.f32 %0, %1;" : "=f"(r) : "f"(x)); return r;
}
__device__ __forceinline__ float fast_lg2(float x) {
    float r; asm("lg2.approx.ftz.f32 %0, %1;" : "=f"(r) : "f"(x)); return r;
}
__device__ __forceinline__ void fma2(unsigned long long& d, unsigned long long a, unsigned long long b) {
    asm("fma.rn.f32x2 %0, %1, %2, %0;" : "+l"(d) : "l"(a), "l"(b));
}
__device__ __forceinline__ unsigned long long add2(unsigned long long a, unsigned long long b) {
    unsigned long long r; asm("add.rn.f32x2 %0, %1, %2;" : "=l"(r) : "l"(a), "l"(b)); return r;
}
__device__ __forceinline__ unsigned long long pack2(float x, float y) {
    unsigned long long r; asm("mov.b64 %0, {%1, %2};" : "=l"(r) : "f"(x), "f"(y)); return r;
}
__device__ __forceinline__ float2 unpack2(unsigned long long v) {
    float2 f; asm("mov.b64 {%0, %1}, %2;" : "=f"(f.x), "=f"(f.y) : "l"(v)); return f;
}

// One CTA (128 threads) = FOUR batches = two f32x2 pairs A=(b0,b1), B=(b2,b3),
// BOTH stepped every barrier round so each pair's issue hides the other pair's
// latency (barrier release, LDS round-trip, FFMA chains) — guaranteed overlap
// inside one CTA instead of hoping a co-resident CTA lines up.
// Warp w owns tags [16w,16w+16); lane l handles tag 16w+(l&15) and half (l>>4)
// of each 64-term dot (32 FFMA2 per pair). Halves combine via shfl.bfly(16).
//
// Linear-domain state per batch: P[i] = exp(score[i] - M); per step
//   S = E*P ;  P' = S * ex2(emit*log2e - lg2(q)) ;  m2 += lg2(q),  q = P[0].
__global__ __launch_bounds__(128, 2)
void crf_fwd_kernel(const float* __restrict__ h, const float* __restrict__ trans,
                    const int* __restrict__ lengths, float* __restrict__ out,
                    int B, int T)
{
    const int tid  = threadIdx.x;
    const int w    = tid >> 5;
    const int l    = tid & 31;
    const int half = l >> 4;
    const int tag  = w * 16 + (l & 15);
    const int j0   = half * 32;

    const int bbase = blockIdx.x * 4;
    const int b0c = min(bbase + 0, B - 1);
    const int b1c = min(bbase + 1, B - 1);
    const int b2c = min(bbase + 2, B - 1);
    const int b3c = min(bbase + 3, B - 1);

    // [buf][pair][slot]; halves padded 16B apart (slots 0..31 and 34..65)
    __shared__ __align__(16) unsigned long long pbuf[2][2][68];
    __shared__ float4 redm[4];
    __shared__ float4 redy[4];

    // Cache E[tag][j0..j0+32) duplicated into f32x2 (32 u64 regs, shared by pairs)
    unsigned long long rowp[32];
    const float4* trow = reinterpret_cast<const float4*>(trans + tag * NTAGS + j0);
    #pragma unroll
    for (int k = 0; k < 8; k++) {
        float4 tv = trow[k];
        float e0 = fast_ex2(tv.x * LOG2E);
        float e1 = fast_ex2(tv.y * LOG2E);
        float e2 = fast_ex2(tv.z * LOG2E);
        float e3 = fast_ex2(tv.w * LOG2E);
        rowp[4 * k + 0] = pack2(e0, e0);
        rowp[4 * k + 1] = pack2(e1, e1);
        rowp[4 * k + 2] = pack2(e2, e2);
        rowp[4 * k + 3] = pack2(e3, e3);
    }

    const int len0 = (bbase + 0 < B) ? lengths[bbase + 0] : 0;
    const int len1 = (bbase + 1 < B) ? lengths[bbase + 1] : 0;
    const int len2 = (bbase + 2 < B) ? lengths[bbase + 2] : 0;
    const int len3 = (bbase + 3 < B) ? lengths[bbase + 3] : 0;
    const int tmax = max(max(len0, len1), max(len2, len3));

    const int sidx = tag + ((tag >> 5) << 1);   // store slot with 16B half-pad

    // init: START_TAG = N-2 -> p=1, others p=0
    const float init = (tag == NTAGS - 2) ? 1.0f : 0.0f;
    float pxA = init, pyA = init, pxB = init, pyB = init;
    float m0 = 0.0f, m1 = 0.0f, m2 = 0.0f, m3 = 0.0f;  // normalizer accum (log2)

    if (half == 0) {
        pbuf[0][0][sidx] = pack2(pxA, pyA);
        pbuf[0][1][sidx] = pack2(pxB, pyB);
    }
    __syncthreads();

    const float* __restrict__ hp0 = h + (size_t)b0c * T * NTAGS + tag;
    const float* __restrict__ hp1 = h + (size_t)b1c * T * NTAGS + tag;
    const float* __restrict__ hp2 = h + (size_t)b2c * T * NTAGS + tag;
    const float* __restrict__ hp3 = h + (size_t)b3c * T * NTAGS + tag;

    float ea0 = hp0[0], ea1 = hp1[0], ea2 = hp2[0], ea3 = hp3[0];
    const int o1 = (tmax > 1) ? NTAGS : 0;
    float eb0 = hp0[o1], eb1 = hp1[o1], eb2 = hp2[o1], eb3 = hp3[o1];

    int buf = 0;
    for (int t = 0; t < tmax; t++) {
        const ulonglong2* PA =
            reinterpret_cast<const ulonglong2*>(&pbuf[buf][0][half * 34]);
        const ulonglong2* PB =
            reinterpret_cast<const ulonglong2*>(&pbuf[buf][1][half * 34]);

        ulonglong2 uA0 = PA[0], uA1 = PA[1];
        ulonglong2 uB0 = PB[0], uB1 = PB[1];

        float2 qA = unpack2(uA0.x);             // q = P[0] (valid in half==0 lanes)
        float2 qB = unpack2(uB0.x);
        float q0 = (t == 0) ? 1.0f : qA.x;
        float q1 = (t == 0) ? 1.0f : qA.y;
        float q2 = (t == 0) ? 1.0f : qB.x;
        float q3 = (t == 0) ? 1.0f : qB.y;

        unsigned long long aA0 = 0, aA1 = 0, aA2 = 0, aA3 = 0;
        unsigned long long aB0 = 0, aB1 = 0, aB2 = 0, aB3 = 0;
        fma2(aA0, rowp[0], uA0.x); fma2(aA1, rowp[1], uA0.y);
        fma2(aA2, rowp[2], uA1.x); fma2(aA3, rowp[3], uA1.y);
        fma2(aB0, rowp[0], uB0.x); fma2(aB1, rowp[1], uB0.y);
        fma2(aB2, rowp[2], uB1.x); fma2(aB3, rowp[3], uB1.y);

        // normalizer + emission factors on MUFU, overlapped with the dots
        float l20 = fast_lg2(q0), l21 = fast_lg2(q1);
        float l22 = fast_lg2(q2), l23 = fast_lg2(q3);
        float r0 = fast_ex2(fmaf(ea0, LOG2E, -l20));
        float r1 = fast_ex2(fmaf(ea1, LOG2E, -l21));
        float r2 = fast_ex2(fmaf(ea2, LOG2E, -l22));
        float r3 = fast_ex2(fmaf(ea3, LOG2E, -l23));

        #pragma unroll
        for (int k = 2; k < 16; k += 2) {
            ulonglong2 vA0 = PA[k], vA1 = PA[k + 1];
            ulonglong2 vB0 = PB[k], vB1 = PB[k + 1];
            fma2(aA0, rowp[2 * k + 0], vA0.x); fma2(aA1, rowp[2 * k + 1], vA0.y);
            fma2(aA2, rowp[2 * k + 2], vA1.x); fma2(aA3, rowp[2 * k + 3], vA1.y);
            fma2(aB0, rowp[2 * k + 0], vB0.x); fma2(aB1, rowp[2 * k + 1], vB0.y);
            fma2(aB2, rowp[2 * k + 2], vB1.x); fma2(aB3, rowp[2 * k + 3], vB1.y);
        }

        // branch-free emission prefetch for t+2 (clamped offset, in-bounds)
        const int onext = (t + 2 < tmax) ? 2 * NTAGS : 0;
        float ec0 = hp0[onext], ec1 = hp1[onext];
        float ec2 = hp2[onext], ec3 = hp3[onext];
        hp0 += NTAGS; hp1 += NTAGS; hp2 += NTAGS; hp3 += NTAGS;

        float2 slA = unpack2(add2(add2(aA0, aA1), add2(aA2, aA3)));
        float2 slB = unpack2(add2(add2(aB0, aB1), add2(aB2, aB3)));
        float sx0 = slA.x + __shfl_xor_sync(0xffffffffu, slA.x, 16);
        float sx1 = slA.y + __shfl_xor_sync(0xffffffffu, slA.y, 16);
        float sx2 = slB.x + __shfl_xor_sync(0xffffffffu, slB.x, 16);
        float sx3 = slB.y + __shfl_xor_sync(0xffffffffu, slB.y, 16);

        // branch-free masked update (freeze past length)
        const bool k0 = t < len0, k1 = t < len1, k2 = t < len2, k3 = t < len3;
        pxA = k0 ? sx0 * r0 : pxA;  m0 += k0 ? l20 : 0.0f;
        pyA = k1 ? sx1 * r1 : pyA;  m1 += k1 ? l21 : 0.0f;
        pxB = k2 ? sx2 * r2 : pxB;  m2 += k2 ? l22 : 0.0f;
        pyB = k3 ? sx3 * r3 : pyB;  m3 += k3 ? l23 : 0.0f;

        if (half == 0) {
            pbuf[buf ^ 1][0][sidx] = pack2(pxA, pyA);
            pbuf[buf ^ 1][1][sidx] = pack2(pxB, pyB);
        }
        __syncthreads();

        ea0 = eb0; ea1 = eb1; ea2 = eb2; ea3 = eb3;
        eb0 = ec0; eb1 = ec1; eb2 = ec2; eb3 = ec3;
        buf ^= 1;
    }

    // Epilogue: score[i] = LN2*(m2 + lg2(p)); add END transition; exact LSE.
    float te = trans[(NTAGS - 1) * NTAGS + tag];
    float x0 = fmaf(LN2, m0 + fast_lg2(pxA), te);
    float x1 = fmaf(LN2, m1 + fast_lg2(pyA), te);
    float x2 = fmaf(LN2, m2 + fast_lg2(pxB), te);
    float x3 = fmaf(LN2, m3 + fast_lg2(pyB), te);
    if (half) { x0 = -1e30f; x1 = -1e30f; x2 = -1e30f; x3 = -1e30f; }

    float M0 = x0, M1 = x1, M2 = x2, M3 = x3;
    #pragma unroll
    for (int o = 16; o > 0; o >>= 1) {
        M0 = fmaxf(M0, __shfl_xor_sync(0xffffffffu, M0, o));
        M1 = fmaxf(M1, __shfl_xor_sync(0xffffffffu, M1, o));
        M2 = fmaxf(M2, __shfl_xor_sync(0xffffffffu, M2, o));
        M3 = fmaxf(M3, __shfl_xor_sync(0xffffffffu, M3, o));
    }
    if (l == 0) redm[w] = make_float4(M0, M1, M2, M3);
    __syncthreads();
    M0 = fmaxf(fmaxf(redm[0].x, redm[1].x), fmaxf(redm[2].x, redm[3].x));
    M1 = fmaxf(fmaxf(redm[0].y, redm[1].y), fmaxf(redm[2].y, redm[3].y));
    M2 = fmaxf(fmaxf(redm[0].z, redm[1].z), fmaxf(redm[2].z, redm[3].z));
    M3 = fmaxf(fmaxf(redm[0].w, redm[1].w), fmaxf(redm[2].w, redm[3].w));

    float y0 = fast_ex2((x0 - M0) * LOG2E);     // -1e30 lanes contribute 0
    float y1 = fast_ex2((x1 - M1) * LOG2E);
    float y2 = fast_ex2((x2 - M2) * LOG2E);
    float y3 = fast_ex2((x3 - M3) * LOG2E);
    #pragma unroll
    for (int o = 16; o > 0; o >>= 1) {
        y0 += __shfl_xor_sync(0xffffffffu, y0, o);
        y1 += __shfl_xor_sync(0xffffffffu, y1, o);
        y2 += __shfl_xor_sync(0xffffffffu, y2, o);
        y3 += __shfl_xor_sync(0xffffffffu, y3, o);
    }
    if (l == 0) redy[w] = make_float4(y0, y1, y2, y3);
    __syncthreads();

    if (tid == 0) {
        float s0 = (redy[0].x + redy[1].x) + (redy[2].x + redy[3].x);
        float s1 = (redy[0].y + redy[1].y) + (redy[2].y + redy[3].y);
        float s2 = (redy[0].z + redy[1].z) + (redy[2].z + redy[3].z);
        float s3 = (redy[0].w + redy[1].w) + (redy[2].w + redy[3].w);
        if (bbase + 0 < B) out[bbase + 0] = M0 + LN2 * fast_lg2(s0);
        if (bbase + 1 < B) out[bbase + 1] = M1 + LN2 * fast_lg2(s1);
        if (bbase + 2 < B) out[bbase + 2] = M2 + LN2 * fast_lg2(s2);
        if (bbase + 3 < B) out[bbase + 3] = M3 + LN2 * fast_lg2(s3);
    }
}

extern "C" void kernel_launch(void* const* d_in, const int* in_sizes, int n_in,
                              void* d_out, int out_size)
{
    const float* h       = (const float*)d_in[0];   // [B, T, N] f32
    const float* trans   = (const float*)d_in[1];   // [N, N]    f32
    const int*   lengths = (const int*)d_in[2];     // [B]       i32
    float*       out     = (float*)d_out;           // [B]       f32

    const int B = in_sizes[2];
    const int T = in_sizes[0] / (B * NTAGS);

    const int nblk = (B + 3) / 4;
    crf_fwd_kernel<<<nblk, 128>>>(h, trans, lengths, out, B, T);
}

// round 6
// speedup vs baseline: 3.7055x; 3.7055x over previous
#include <cuda_runtime.h>
#include <cuda_bf16.h>

#define NTAGS 64
#define LOG2E 1.4426950408889634f
#define LN2   0.69314718055994531f

__device__ __forceinline__ float fast_ex2(float x) {
    float r; asm("ex2.approx.ftz.f32 %0, %1;" : "=f"(r) : "f"(x)); return r;
}
__device__ __forceinline__ float fast_lg2(float x) {
    float r; asm("lg2.approx.ftz.f32 %0, %1;" : "=f"(r) : "f"(x)); return r;
}
__device__ __forceinline__ void fma2(unsigned long long& d, unsigned long long a, unsigned long long b) {
    asm("fma.rn.f32x2 %0, %1, %2, %0;" : "+l"(d) : "l"(a), "l"(b));
}
__device__ __forceinline__ unsigned long long add2(unsigned long long a, unsigned long long b) {
    unsigned long long r; asm("add.rn.f32x2 %0, %1, %2;" : "=l"(r) : "l"(a), "l"(b)); return r;
}
__device__ __forceinline__ unsigned long long pack2(float x, float y) {
    unsigned long long r; asm("mov.b64 %0, {%1, %2};" : "=l"(r) : "f"(x), "f"(y)); return r;
}
__device__ __forceinline__ float2 unpack2(unsigned long long v) {
    float2 f; asm("mov.b64 {%0, %1}, %2;" : "=f"(f.x), "=f"(f.y) : "l"(v)); return f;
}

// One CTA (128 threads) = ONE batch pair, TIME-SPLIT:
//   threads   0..63  (warps 0,1, SMSP 0,1): FORWARD  half  P <- diag(f_t)E P, t ascending
//   threads  64..127 (warps 2,3, SMSP 2,3): BACKWARD half  A <- E^T(f_t (*) A), t descending
// Serial depth = ceil(len/2) instead of len. One __syncthreads per round couples
// the two directions, but their work runs in PARALLEL warps on different SMSPs.
// Lane owns one tag (full 64-term dot, 64 x FFMA2 on f32x2-packed batch pair).
//
// Linear-domain normalization: each round divides the stored vector by its
// element 0 (q) and accumulates lg2(q); emission factors are folded via
// ex2(emit*log2e - lg2 q) off the critical path. The backward group's register
// always carries one extra folded emission (e_last), divided out in the epilogue.
__global__ __launch_bounds__(128, 2)
void crf_fwd_kernel(const float* __restrict__ h, const float* __restrict__ trans,
                    const int* __restrict__ lengths, float* __restrict__ out,
                    int B, int T)
{
    const int tid = threadIdx.x;
    const int g   = tid >> 6;              // 0 = forward, 1 = backward
    const int tag = tid & 63;

    const int b0  = blockIdx.x * 2;
    const int b1v = b0 + 1;
    const int b1  = min(b1v, B - 1);

    __shared__ __align__(16) unsigned long long pbuf[2][2][NTAGS]; // [group][buf][tag]
    __shared__ __align__(16) unsigned long long fin[2][NTAGS];     // final vectors
    __shared__ float2 fm2[2];                                      // log2 normalizer sums

    const int len0 = lengths[b0];
    const int len1 = lengths[b1];
    const int mid0 = (len0 + 1) >> 1;
    const int mid1 = (len1 + 1) >> 1;
    const int rounds = max(mid0, mid1);               // CTA-uniform
    const int act0 = g ? (len0 - mid0) : mid0;        // active rounds per component
    const int act1 = g ? (len1 - mid1) : mid1;

    // cache exp(trans): forward lanes cache row tag, backward lanes cache column tag
    unsigned long long rowp[NTAGS];
    {
        const int base   = g ? tag : tag * NTAGS;
        const int stride = g ? NTAGS : 1;
        #pragma unroll
        for (int j = 0; j < NTAGS; j++) {
            float e = fast_ex2(trans[base + j * stride] * LOG2E);
            rowp[j] = pack2(e, e);
        }
    }

    const float* __restrict__ hb0 = h + (size_t)b0 * T * NTAGS + tag;
    const float* __restrict__ hb1 = h + (size_t)b1 * T * NTAGS + tag;

    // initial state + first store
    float px, py, el0 = 0.0f, el1 = 0.0f;   // el* = emission currently folded (bwd)
    if (g == 0) {
        px = (tag == NTAGS - 2) ? 1.0f : 0.0f;   // START_TAG = N-2
        py = px;
    } else {
        float uval = fast_ex2(trans[(NTAGS - 1) * NTAGS + tag] * LOG2E); // END row
        el0 = hb0[(size_t)(len0 - 1) * NTAGS];
        el1 = hb1[(size_t)(len1 - 1) * NTAGS];
        px = uval * fast_ex2(el0 * LOG2E);
        py = uval * fast_ex2(el1 * LOG2E);
    }
    float m20 = 0.0f, m21 = 0.0f;

    pbuf[g][0][tag] = pack2(px, py);
    __syncthreads();

    // emission pipeline, 2 deep. index at round r: fwd r ; bwd max(len-2-r, 0)
    const int Tm1 = T - 1;
    int i0a = g ? max(len0 - 2, 0) : 0;
    int i1a = g ? max(len1 - 2, 0) : 0;
    int i0b = g ? max(len0 - 3, 0) : min(1, Tm1);
    int i1b = g ? max(len1 - 3, 0) : min(1, Tm1);
    float ea0 = hb0[(size_t)i0a * NTAGS];
    float ea1 = hb1[(size_t)i1a * NTAGS];
    float eb0 = hb0[(size_t)i0b * NTAGS];
    float eb1 = hb1[(size_t)i1b * NTAGS];

    int buf = 0;
    for (int r = 0; r < rounds; r++) {
        const ulonglong2* Pv = reinterpret_cast<const ulonglong2*>(pbuf[g][buf]);

        ulonglong2 u0 = Pv[0];
        ulonglong2 u1 = Pv[1];
        float2 qq = unpack2(u0.x);                 // normalizer q = vec[0]
        const bool q1sel = (g == 0) & (r == 0);    // fwd round 0: vec[0] == 0
        float qx = q1sel ? 1.0f : qq.x;
        float qy = q1sel ? 1.0f : qq.y;

        unsigned long long a0 = 0, a1 = 0, a2 = 0, a3 = 0;
        fma2(a0, rowp[0], u0.x); fma2(a1, rowp[1], u0.y);
        fma2(a2, rowp[2], u1.x); fma2(a3, rowp[3], u1.y);

        // normalizer + emission factor on MUFU, overlapped with the dot
        float l2x = fast_lg2(qx);
        float l2y = fast_lg2(qy);
        float rx  = fast_ex2(fmaf(ea0, LOG2E, -l2x));
        float ry  = fast_ex2(fmaf(ea1, LOG2E, -l2y));

        #pragma unroll
        for (int k = 2; k < 32; k += 2) {
            ulonglong2 v0 = Pv[k];
            ulonglong2 v1 = Pv[k + 1];
            fma2(a0, rowp[2 * k + 0], v0.x);
            fma2(a1, rowp[2 * k + 1], v0.y);
            fma2(a2, rowp[2 * k + 2], v1.x);
            fma2(a3, rowp[2 * k + 3], v1.y);
        }

        // prefetch emissions for round r+2 (clamped, memory-safe)
        int n0 = g ? max(len0 - 4 - r, 0) : min(r + 2, Tm1);
        int n1 = g ? max(len1 - 4 - r, 0) : min(r + 2, Tm1);
        float ec0 = hb0[(size_t)n0 * NTAGS];
        float ec1 = hb1[(size_t)n1 * NTAGS];

        float2 S = unpack2(add2(add2(a0, a1), add2(a2, a3)));

        // masked update (freeze past this component's active rounds)
        const bool k0 = r < act0;
        const bool k1 = r < act1;
        px   = k0 ? S.x * rx : px;   m20 += k0 ? l2x : 0.0f;
        py   = k1 ? S.y * ry : py;   m21 += k1 ? l2y : 0.0f;
        el0  = k0 ? ea0 : el0;       // emission folded into current px (bwd)
        el1  = k1 ? ea1 : el1;

        pbuf[g][buf ^ 1][tag] = pack2(px, py);
        __syncthreads();

        ea0 = eb0; ea1 = eb1;
        eb0 = ec0; eb1 = ec1;
        buf ^= 1;
    }

    // Epilogue. Backward register carries one extra folded emission: divide out.
    float c0 = g ? fast_ex2(-el0 * LOG2E) : 1.0f;
    float c1 = g ? fast_ex2(-el1 * LOG2E) : 1.0f;
    fin[g][tag] = pack2(px * c0, py * c1);
    if (tag == 0) fm2[g] = make_float2(m20, m21);
    __syncthreads();

    // answer_b = LN2 * (m2F_b + m2B_b + lg2( sum_i P_b[i] * A_b[i] ))
    if (tid < 32) {
        float2 Fa = unpack2(fin[0][tid]);
        float2 Fb = unpack2(fin[0][tid + 32]);
        float2 Aa = unpack2(fin[1][tid]);
        float2 Ab = unpack2(fin[1][tid + 32]);
        float sx = Fa.x * Aa.x + Fb.x * Ab.x;
        float sy = Fa.y * Aa.y + Fb.y * Ab.y;
        #pragma unroll
        for (int o = 16; o > 0; o >>= 1) {
            sx += __shfl_xor_sync(0xffffffffu, sx, o);
            sy += __shfl_xor_sync(0xffffffffu, sy, o);
        }
        if (tid == 0) {
            float2 mF = fm2[0];
            float2 mB = fm2[1];
            out[b0] = LN2 * (mF.x + mB.x + fast_lg2(sx));
            if (b1v < B) out[b1v] = LN2 * (mF.y + mB.y + fast_lg2(sy));
        }
    }
}

extern "C" void kernel_launch(void* const* d_in, const int* in_sizes, int n_in,
                              void* d_out, int out_size)
{
    const float* h       = (const float*)d_in[0];   // [B, T, N] f32
    const float* trans   = (const float*)d_in[1];   // [N, N]    f32
    const int*   lengths = (const int*)d_in[2];     // [B]       i32
    float*       out     = (float*)d_out;           // [B]       f32

    const int B = in_sizes[2];
    const int T = in_sizes[0] / (B * NTAGS);

    const int nblk = (B + 1) / 2;
    crf_fwd_kernel<<<nblk, 128>>>(h, trans, lengths, out, B, T);
}